// round 8
// baseline (speedup 1.0000x reference)
#include <cuda_runtime.h>
#include <cstdint>

#define NB 4
#define NQ 2048
#define NK 2048
#define ND 1024

// ---------------- device scratch (no runtime allocation allowed) ----------------
__device__ float g_e[NB * NK];                         // exp(rowsum(value)/32)
__device__ float g_vr[(size_t)NB * NK * ND];           // value pre-rounded to tf32
__device__ float g_w[(size_t)NB * NQ * NK];            // weights scratch (if not in d_out)
__device__ float g_ctx[(size_t)NB * NQ * ND];          // context scratch (if not in d_out)

// ---------------- helpers ----------------
__device__ __forceinline__ uint32_t smem_u32(const void* p) {
    uint32_t a;
    asm("{ .reg .u64 t; cvta.to.shared.u64 t, %1; cvt.u32.u64 %0, t; }" : "=r"(a) : "l"(p));
    return a;
}

__device__ __forceinline__ void cp16(uint32_t s, const void* g) {
    asm volatile("cp.async.cg.shared.global [%0], [%1], 16;\n" :: "r"(s), "l"(g));
}

__device__ __forceinline__ float tf32r(float x) {
    float r;
    asm("cvt.rna.tf32.f32 %0, %1;" : "=f"(r) : "f"(x));
    return r;
}

__device__ __forceinline__ float lds32(uint32_t a) {
    float v;
    asm volatile("ld.shared.b32 %0, [%1];" : "=f"(v) : "r"(a));
    return v;
}

// ---------------- kernel 1: e[b,k] = exp(rowsum(value)/32) ----------------
__global__ void k_rowexp(const float* __restrict__ v) {
    int row = blockIdx.x;  // b*NK + k
    const float4* p = reinterpret_cast<const float4*>(v + (size_t)row * ND);
    float4 f = p[threadIdx.x];
    float s = (f.x + f.y) + (f.z + f.w);
#pragma unroll
    for (int o = 16; o; o >>= 1) s += __shfl_xor_sync(0xffffffffu, s, o);
    __shared__ float sh[8];
    if ((threadIdx.x & 31) == 0) sh[threadIdx.x >> 5] = s;
    __syncthreads();
    if (threadIdx.x == 0) {
        float t = 0.f;
#pragma unroll
        for (int i = 0; i < 8; i++) t += sh[i];
        g_e[row] = expf(t * 0.03125f);  // / sqrt(1024)
    }
}

// ---------------- kernel 2: g_vr = round_to_tf32(value) ----------------
__global__ void k_round(const float* __restrict__ v) {
    size_t i = ((size_t)blockIdx.x * 256 + threadIdx.x);
    const float4* src = reinterpret_cast<const float4*>(v);
    float4* dst = reinterpret_cast<float4*>(g_vr);
    size_t n4 = (size_t)NB * NK * ND / 4;
    for (; i < n4; i += (size_t)gridDim.x * 256) {
        float4 f = src[i];
        f.x = tf32r(f.x); f.y = tf32r(f.y); f.z = tf32r(f.z); f.w = tf32r(f.w);
        dst[i] = f;
    }
}

// ---------------- kernel 3: weights (softmax closed form) ----------------
// scores = (q_sum[q] + k_sum[k])/32 + mask_bias; q_sum is constant along the
// softmax axis so it cancels: w[b,q,k] = mask * e[b,k] / sum_k(mask * e[b,k]).
// Written tf32-rounded so the GEMM consumes it bit-exactly.
__global__ void k_weights(const int* __restrict__ mask, float* __restrict__ w) {
    int row = blockIdx.x;      // b*NQ + q
    int b = row >> 11;
    const int4* m4 = reinterpret_cast<const int4*>(mask + (size_t)row * NK);
    const float4* e4 = reinterpret_cast<const float4*>(g_e + b * NK);
    float4* w4 = reinterpret_cast<float4*>(w + (size_t)row * NK);
    float s = 0.f;
#pragma unroll
    for (int i = threadIdx.x; i < NK / 4; i += 256) {
        int4 m = m4[i];
        float4 e = e4[i];
        s += (m.x ? e.x : 0.f) + (m.y ? e.y : 0.f) + (m.z ? e.z : 0.f) + (m.w ? e.w : 0.f);
    }
#pragma unroll
    for (int o = 16; o; o >>= 1) s += __shfl_xor_sync(0xffffffffu, s, o);
    __shared__ float sh[8];
    __shared__ float shi;
    if ((threadIdx.x & 31) == 0) sh[threadIdx.x >> 5] = s;
    __syncthreads();
    if (threadIdx.x == 0) {
        float t = 0.f;
#pragma unroll
        for (int i = 0; i < 8; i++) t += sh[i];
        shi = 1.0f / t;
    }
    __syncthreads();
    float inv = shi;
#pragma unroll
    for (int i = threadIdx.x; i < NK / 4; i += 256) {
        int4 m = m4[i];
        float4 e = e4[i];
        float4 o;
        o.x = m.x ? tf32r(e.x * inv) : 0.f;
        o.y = m.y ? tf32r(e.y * inv) : 0.f;
        o.z = m.z ? tf32r(e.z * inv) : 0.f;
        o.w = m.w ? tf32r(e.w * inv) : 0.f;
        w4[i] = o;
    }
}

// ---------------- kernel 4: context = w @ value  (tf32 mma.sync) ----------------
// CTA tile 128x128x32, 8 warps in 2(M) x 4(N), warp tile 64x32.
#define BM 128
#define BN 128
#define BK 32
#define NT (NK / BK)       // 64
#define ASTRIDE 36         // floats per A smem row (frag banks 4g+t4: conflict-free)
#define BSTRIDE 136        // floats per B smem row (128 data + 8 pad; frag banks 8t4+g: conflict-free)
#define ABYTES (BM * ASTRIDE * 4)            // 18432
#define BBYTES (BK * BSTRIDE * 4)            // 17408
#define STAGE_BYTES (ABYTES + BBYTES)        // 35840
#define STAGES 3
#define SMEM_GEMM (STAGES * STAGE_BYTES)     // 107520

__global__ void __launch_bounds__(256, 1)
k_gemm(const float* __restrict__ w, float* __restrict__ ctx) {
    extern __shared__ char smem[];
    uint32_t sb = smem_u32(smem);
    int tid = threadIdx.x, wid = tid >> 5, lane = tid & 31;
    int g = lane >> 2, t4 = lane & 3;
    int d0 = blockIdx.x * BN;
    int q0 = blockIdx.y * BM;
    int b = blockIdx.z;
    int wm = (wid >> 2) * 64;   // warp M offset in CTA tile
    int wn = (wid & 3) * 32;    // warp N offset in CTA tile

    const float* Ag = w + (size_t)(b * NQ + q0) * NK;         // [128 rows q][k]
    const float* Bg = g_vr + (size_t)b * NK * ND + d0;        // [k][128 cols d]

    auto load_tile = [&](int t, int s) {
        int k0 = t * BK;
        uint32_t As = sb + s * STAGE_BYTES;
        uint32_t Bs = As + ABYTES;
#pragma unroll
        for (int j = 0; j < 4; j++) {   // A: 128 rows x 32 floats = 1024 x 16B
            int task = tid + j * 256;
            int r = task >> 3, c = task & 7;
            cp16(As + (uint32_t)(r * (ASTRIDE * 4) + c * 16),
                 Ag + (size_t)r * NK + k0 + c * 4);
        }
#pragma unroll
        for (int j = 0; j < 4; j++) {   // B: 32 rows x 128 floats = 1024 x 16B
            int task = tid + j * 256;
            int r = task >> 5, c = task & 31;
            cp16(Bs + (uint32_t)(r * (BSTRIDE * 4) + c * 16),
                 Bg + (size_t)(k0 + r) * ND + c * 4);
        }
        asm volatile("cp.async.commit_group;\n" ::: "memory");
    };

    float acc[4][4][4];
#pragma unroll
    for (int m = 0; m < 4; m++)
#pragma unroll
        for (int n = 0; n < 4; n++)
#pragma unroll
            for (int i = 0; i < 4; i++) acc[m][n][i] = 0.f;

    load_tile(0, 0);
    load_tile(1, 1);

#pragma unroll 1
    for (int t = 0; t < NT; t++) {
        if (t + 2 < NT) asm volatile("cp.async.wait_group 1;\n" ::: "memory");
        else            asm volatile("cp.async.wait_group 0;\n" ::: "memory");
        __syncthreads();
        if (t + 2 < NT) load_tile(t + 2, (t + 2) % 3);

        uint32_t As = sb + (t % 3) * STAGE_BYTES;
        uint32_t Bs = As + ABYTES;
#pragma unroll
        for (int c = 0; c < 4; c++) {
            int kc = c * 8;
            float a[4][4], bf[4][2];
#pragma unroll
            for (int m = 0; m < 4; m++) {
                uint32_t base = As + (uint32_t)(((wm + m * 16 + g) * ASTRIDE + kc + t4) * 4);
                a[m][0] = lds32(base);
                a[m][1] = lds32(base + 8 * ASTRIDE * 4);
                a[m][2] = lds32(base + 16);
                a[m][3] = lds32(base + 8 * ASTRIDE * 4 + 16);
            }
#pragma unroll
            for (int n = 0; n < 4; n++) {
                uint32_t base = Bs + (uint32_t)(((kc + t4) * BSTRIDE + wn + n * 8 + g) * 4);
                bf[n][0] = lds32(base);
                bf[n][1] = lds32(base + 4 * BSTRIDE * 4);
            }
#pragma unroll
            for (int m = 0; m < 4; m++)
#pragma unroll
                for (int n = 0; n < 4; n++) {
                    asm volatile(
                        "mma.sync.aligned.m16n8k8.row.col.f32.tf32.tf32.f32 "
                        "{%0,%1,%2,%3}, {%4,%5,%6,%7}, {%8,%9}, {%0,%1,%2,%3};"
                        : "+f"(acc[m][n][0]), "+f"(acc[m][n][1]),
                          "+f"(acc[m][n][2]), "+f"(acc[m][n][3])
                        : "r"(__float_as_uint(a[m][0])), "r"(__float_as_uint(a[m][1])),
                          "r"(__float_as_uint(a[m][2])), "r"(__float_as_uint(a[m][3])),
                          "r"(__float_as_uint(bf[n][0])), "r"(__float_as_uint(bf[n][1])));
                }
        }
    }

    // epilogue: c0=(g,2t), c1=(g,2t+1), c2=(g+8,2t), c3=(g+8,2t+1)
#pragma unroll
    for (int m = 0; m < 4; m++) {
        int row = q0 + wm + m * 16 + g;
#pragma unroll
        for (int n = 0; n < 4; n++) {
            int col = d0 + wn + n * 8 + 2 * t4;
            float* p0 = ctx + (size_t)(b * NQ + row) * ND + col;
            float* p1 = ctx + (size_t)(b * NQ + row + 8) * ND + col;
            *reinterpret_cast<float2*>(p0) = make_float2(acc[m][n][0], acc[m][n][1]);
            *reinterpret_cast<float2*>(p1) = make_float2(acc[m][n][2], acc[m][n][3]);
        }
    }
}

// ---------------- launcher ----------------
extern "C" void kernel_launch(void* const* d_in, const int* in_sizes, int n_in,
                              void* d_out, int out_size) {
    // inputs: [0]=query (UNUSED: q_sum cancels in softmax), [1]=value, [2]=attention_mask
    const float* value = (const float*)d_in[1];
    const int* mask = (const int*)d_in[2];

    const size_t CTXN = (size_t)NB * NQ * ND;   // 8,388,608
    const size_t WN   = (size_t)NB * NQ * NK;   // 16,777,216

    // Resolve output layout from out_size (defensive: never write past d_out).
    float* ctx;
    float* w;
    void* scr_w = nullptr;
    void* scr_ctx = nullptr;
    cudaGetSymbolAddress(&scr_w, g_w);
    cudaGetSymbolAddress(&scr_ctx, g_ctx);

    if ((size_t)out_size >= CTXN + WN) {
        // [context | attention_weights] concatenated (tuple order)
        ctx = (float*)d_out;
        w = (float*)d_out + CTXN;
    } else if ((size_t)out_size == WN) {
        // weights-only output
        w = (float*)d_out;
        ctx = (float*)scr_ctx;
    } else {
        // context-only output; weights live in scratch (still needed as GEMM A)
        ctx = (float*)d_out;
        w = (float*)scr_w;
    }

    cudaFuncSetAttribute(k_gemm, cudaFuncAttributeMaxDynamicSharedMemorySize, SMEM_GEMM);

    k_rowexp<<<NB * NK, 256>>>(value);
    k_round<<<1024, 256>>>(value);
    k_weights<<<NB * NQ, 256>>>(mask, w);
    k_gemm<<<dim3(ND / BN, NQ / BM, NB), 256, SMEM_GEMM>>>(w, ctx);
}

// round 10
// speedup vs baseline: 1.1313x; 1.1313x over previous
#include <cuda_runtime.h>
#include <cstdint>

#define NB 4
#define NQ 2048
#define NK 2048
#define ND 1024

// ---------------- device scratch (no runtime allocation allowed) ----------------
__device__ float g_e[NB * NK];                         // exp(rowsum(value)/32)
__device__ float g_w[(size_t)NB * NQ * NK];            // weights scratch (if not in d_out)
__device__ float g_ctx[(size_t)NB * NQ * ND];          // context scratch (if not in d_out)

// ---------------- helpers ----------------
__device__ __forceinline__ uint32_t smem_u32(const void* p) {
    uint32_t a;
    asm("{ .reg .u64 t; cvta.to.shared.u64 t, %1; cvt.u32.u64 %0, t; }" : "=r"(a) : "l"(p));
    return a;
}

__device__ __forceinline__ void cp16(uint32_t s, const void* g) {
    asm volatile("cp.async.cg.shared.global [%0], [%1], 16;\n" :: "r"(s), "l"(g));
}

__device__ __forceinline__ float tf32r(float x) {
    float r;
    asm("cvt.rna.tf32.f32 %0, %1;" : "=f"(r) : "f"(x));
    return r;
}

__device__ __forceinline__ float lds32(uint32_t a) {
    float v;
    asm volatile("ld.shared.b32 %0, [%1];" : "=f"(v) : "r"(a));
    return v;
}

// ---------------- kernel 1: e[b,k] = exp(rowsum(value)/32) ----------------
__global__ void k_rowexp(const float* __restrict__ v) {
    int row = blockIdx.x;  // b*NK + k
    const float4* p = reinterpret_cast<const float4*>(v + (size_t)row * ND);
    float4 f = p[threadIdx.x];
    float s = (f.x + f.y) + (f.z + f.w);
#pragma unroll
    for (int o = 16; o; o >>= 1) s += __shfl_xor_sync(0xffffffffu, s, o);
    __shared__ float sh[8];
    if ((threadIdx.x & 31) == 0) sh[threadIdx.x >> 5] = s;
    __syncthreads();
    if (threadIdx.x == 0) {
        float t = 0.f;
#pragma unroll
        for (int i = 0; i < 8; i++) t += sh[i];
        g_e[row] = expf(t * 0.03125f);  // / sqrt(1024)
    }
}

// ---------------- kernel 2: weights (softmax closed form) ----------------
// scores = (q_sum[q] + k_sum[k])/32 + mask_bias; q_sum is constant along the
// softmax axis so it cancels: w[b,q,k] = mask * e[b,k] / sum_k(mask * e[b,k]).
// Written tf32-RNA-rounded (w is all-positive: truncation there would bias).
__global__ void k_weights(const int* __restrict__ mask, float* __restrict__ w) {
    int row = blockIdx.x;      // b*NQ + q
    int b = row >> 11;
    const int4* m4 = reinterpret_cast<const int4*>(mask + (size_t)row * NK);
    const float4* e4 = reinterpret_cast<const float4*>(g_e + b * NK);
    float4* w4 = reinterpret_cast<float4*>(w + (size_t)row * NK);
    float s = 0.f;
#pragma unroll
    for (int i = threadIdx.x; i < NK / 4; i += 256) {
        int4 m = m4[i];
        float4 e = e4[i];
        s += (m.x ? e.x : 0.f) + (m.y ? e.y : 0.f) + (m.z ? e.z : 0.f) + (m.w ? e.w : 0.f);
    }
#pragma unroll
    for (int o = 16; o; o >>= 1) s += __shfl_xor_sync(0xffffffffu, s, o);
    __shared__ float sh[8];
    __shared__ float shi;
    if ((threadIdx.x & 31) == 0) sh[threadIdx.x >> 5] = s;
    __syncthreads();
    if (threadIdx.x == 0) {
        float t = 0.f;
#pragma unroll
        for (int i = 0; i < 8; i++) t += sh[i];
        shi = 1.0f / t;
    }
    __syncthreads();
    float inv = shi;
#pragma unroll
    for (int i = threadIdx.x; i < NK / 4; i += 256) {
        int4 m = m4[i];
        float4 e = e4[i];
        float4 o;
        o.x = m.x ? tf32r(e.x * inv) : 0.f;
        o.y = m.y ? tf32r(e.y * inv) : 0.f;
        o.z = m.z ? tf32r(e.z * inv) : 0.f;
        o.w = m.w ? tf32r(e.w * inv) : 0.f;
        w4[i] = o;
    }
}

// ---------------- kernel 3: context = w @ value  (tf32 mma.sync) ----------------
// CTA tile 128x128x32, 8 warps in 2(M) x 4(N), warp tile 64x32, 2 CTAs/SM.
// B reads `value` raw; fragments rounded in-register (value is zero-mean, and
// we RNA-round anyway — fma pipe is idle).
#define BM 128
#define BN 128
#define BK 32
#define NT (NK / BK)       // 64
#define ASTRIDE 36         // floats per A smem row (frag banks 4g+t4: conflict-free)
#define BSTRIDE 136        // floats per B smem row (128 data + 8 pad; frag banks 8t4+g: conflict-free)
#define ABYTES (BM * ASTRIDE * 4)            // 18432
#define BBYTES (BK * BSTRIDE * 4)            // 17408
#define STAGE_BYTES (ABYTES + BBYTES)        // 35840
#define STAGES 3
#define SMEM_GEMM (STAGES * STAGE_BYTES)     // 107520  (x2 CTAs = 210KB <= 228KB/SM)

__global__ void __launch_bounds__(256, 2)
k_gemm(const float* __restrict__ w, const float* __restrict__ value,
       float* __restrict__ ctx) {
    extern __shared__ char smem[];
    uint32_t sb = smem_u32(smem);
    int tid = threadIdx.x, wid = tid >> 5, lane = tid & 31;
    int g = lane >> 2, t4 = lane & 3;
    int d0 = blockIdx.x * BN;
    int q0 = blockIdx.y * BM;
    int b = blockIdx.z;
    int wm = (wid >> 2) * 64;   // warp M offset in CTA tile
    int wn = (wid & 3) * 32;    // warp N offset in CTA tile

    const float* Ag = w + (size_t)(b * NQ + q0) * NK;        // [128 rows q][k]
    const float* Bg = value + (size_t)b * NK * ND + d0;      // [k][128 cols d]

    // per-thread invariant offsets (u32: tile-local extents are small)
    const uint32_t a_goff = (uint32_t)((tid >> 3) * NK + (tid & 7) * 4);  // element offset
    const uint32_t b_goff = (uint32_t)((tid >> 5) * ND + (tid & 31) * 4);
    const uint32_t a_soff = (uint32_t)((tid >> 3) * (ASTRIDE * 4) + (tid & 7) * 16);
    const uint32_t b_soff = (uint32_t)((tid >> 5) * (BSTRIDE * 4) + (tid & 31) * 16);

    auto load_tile = [&](int t, int s) {
        uint32_t k0 = (uint32_t)t * BK;
        uint32_t As = sb + s * STAGE_BYTES;
        uint32_t Bs = As + ABYTES;
        const float* ap = Ag + a_goff + k0;
        const float* bp = Bg + (size_t)(k0) * ND + b_goff;
#pragma unroll
        for (int j = 0; j < 4; j++)   // A: 128 rows x 32 floats, +32 rows per j
            cp16(As + a_soff + (uint32_t)j * (32 * ASTRIDE * 4), ap + (size_t)j * 32 * NK);
#pragma unroll
        for (int j = 0; j < 4; j++)   // B: 32 rows x 128 floats, +8 rows per j
            cp16(Bs + b_soff + (uint32_t)j * (8 * BSTRIDE * 4), bp + (size_t)j * 8 * ND);
        asm volatile("cp.async.commit_group;\n" ::: "memory");
    };

    float acc[4][4][4];
#pragma unroll
    for (int m = 0; m < 4; m++)
#pragma unroll
        for (int n = 0; n < 4; n++)
#pragma unroll
            for (int i = 0; i < 4; i++) acc[m][n][i] = 0.f;

    load_tile(0, 0);
    load_tile(1, 1);

    // warp-invariant fragment base offsets
    const uint32_t afrag0 = (uint32_t)(((wm + g) * ASTRIDE + t4) * 4);
    const uint32_t bfrag0 = (uint32_t)((t4 * BSTRIDE + wn + g) * 4);

#pragma unroll 1
    for (int t = 0; t < NT; t++) {
        if (t + 2 < NT) asm volatile("cp.async.wait_group 1;\n" ::: "memory");
        else            asm volatile("cp.async.wait_group 0;\n" ::: "memory");
        __syncthreads();
        if (t + 2 < NT) load_tile(t + 2, (t + 2) % 3);

        uint32_t As = sb + (t % 3) * STAGE_BYTES;
        uint32_t Bs = As + ABYTES;
#pragma unroll
        for (int c = 0; c < 4; c++) {
            float a[4][4], bf[4][2];
#pragma unroll
            for (int m = 0; m < 4; m++) {
                uint32_t base = As + afrag0 + (uint32_t)(m * 16 * ASTRIDE * 4 + c * 32);
                a[m][0] = lds32(base);
                a[m][1] = lds32(base + 8 * ASTRIDE * 4);
                a[m][2] = lds32(base + 16);
                a[m][3] = lds32(base + 8 * ASTRIDE * 4 + 16);
            }
#pragma unroll
            for (int n = 0; n < 4; n++) {
                uint32_t base = Bs + bfrag0 + (uint32_t)(c * 8 * BSTRIDE * 4 + n * 32);
                bf[n][0] = tf32r(lds32(base));
                bf[n][1] = tf32r(lds32(base + 4 * BSTRIDE * 4));
            }
#pragma unroll
            for (int m = 0; m < 4; m++)
#pragma unroll
                for (int n = 0; n < 4; n++) {
                    asm volatile(
                        "mma.sync.aligned.m16n8k8.row.col.f32.tf32.tf32.f32 "
                        "{%0,%1,%2,%3}, {%4,%5,%6,%7}, {%8,%9}, {%0,%1,%2,%3};"
                        : "+f"(acc[m][n][0]), "+f"(acc[m][n][1]),
                          "+f"(acc[m][n][2]), "+f"(acc[m][n][3])
                        : "r"(__float_as_uint(a[m][0])), "r"(__float_as_uint(a[m][1])),
                          "r"(__float_as_uint(a[m][2])), "r"(__float_as_uint(a[m][3])),
                          "r"(__float_as_uint(bf[n][0])), "r"(__float_as_uint(bf[n][1])));
                }
        }
    }

    // epilogue: c0=(g,2t), c1=(g,2t+1), c2=(g+8,2t), c3=(g+8,2t+1)
#pragma unroll
    for (int m = 0; m < 4; m++) {
        int row = q0 + wm + m * 16 + g;
#pragma unroll
        for (int n = 0; n < 4; n++) {
            int col = d0 + wn + n * 8 + 2 * t4;
            float* p0 = ctx + (size_t)(b * NQ + row) * ND + col;
            float* p1 = ctx + (size_t)(b * NQ + row + 8) * ND + col;
            *reinterpret_cast<float2*>(p0) = make_float2(acc[m][n][0], acc[m][n][1]);
            *reinterpret_cast<float2*>(p1) = make_float2(acc[m][n][2], acc[m][n][3]);
        }
    }
}

// ---------------- launcher ----------------
extern "C" void kernel_launch(void* const* d_in, const int* in_sizes, int n_in,
                              void* d_out, int out_size) {
    // inputs: [0]=query (UNUSED: q_sum cancels in softmax), [1]=value, [2]=attention_mask
    const float* value = (const float*)d_in[1];
    const int* mask = (const int*)d_in[2];

    const size_t CTXN = (size_t)NB * NQ * ND;   // 8,388,608
    const size_t WN   = (size_t)NB * NQ * NK;   // 16,777,216

    // Resolve output layout from out_size (defensive: never write past d_out).
    float* ctx;
    float* w;
    void* scr_w = nullptr;
    void* scr_ctx = nullptr;
    cudaGetSymbolAddress(&scr_w, g_w);
    cudaGetSymbolAddress(&scr_ctx, g_ctx);

    if ((size_t)out_size >= CTXN + WN) {
        // [context | attention_weights] concatenated (tuple order)
        ctx = (float*)d_out;
        w = (float*)d_out + CTXN;
    } else if ((size_t)out_size == WN) {
        // weights-only output
        w = (float*)d_out;
        ctx = (float*)scr_ctx;
    } else {
        // context-only output; weights live in scratch (still needed as GEMM A)
        ctx = (float*)d_out;
        w = (float*)scr_w;
    }

    cudaFuncSetAttribute(k_gemm, cudaFuncAttributeMaxDynamicSharedMemorySize, SMEM_GEMM);

    k_rowexp<<<NB * NK, 256>>>(value);
    k_weights<<<NB * NQ, 256>>>(mask, w);
    k_gemm<<<dim3(ND / BN, NQ / BM, NB), 256, SMEM_GEMM>>>(w, value, ctx);
}

// round 12
// speedup vs baseline: 1.2294x; 1.0867x over previous
#include <cuda_runtime.h>
#include <cstdint>

#define NB 4
#define NQ 2048
#define NK 2048
#define ND 1024

// ---------------- device scratch (no runtime allocation allowed) ----------------
__device__ float g_e[NB * NK];                         // exp(rowsum(value)/32)
__device__ float g_w[(size_t)NB * NQ * NK];            // weights scratch (if not in d_out)
__device__ float g_ctx[(size_t)NB * NQ * ND];          // context scratch (if not in d_out)

// ---------------- helpers ----------------
__device__ __forceinline__ uint32_t smem_u32(const void* p) {
    uint32_t a;
    asm("{ .reg .u64 t; cvta.to.shared.u64 t, %1; cvt.u32.u64 %0, t; }" : "=r"(a) : "l"(p));
    return a;
}

__device__ __forceinline__ void cp16(uint32_t s, const void* g) {
    asm volatile("cp.async.cg.shared.global [%0], [%1], 16;\n" :: "r"(s), "l"(g));
}

__device__ __forceinline__ float tf32r(float x) {
    float r;
    asm("cvt.rna.tf32.f32 %0, %1;" : "=f"(r) : "f"(x));
    return r;
}

__device__ __forceinline__ float lds32(uint32_t a) {
    float v;
    asm volatile("ld.shared.b32 %0, [%1];" : "=f"(v) : "r"(a));
    return v;
}

// ldmatrix x4: four 8x4-float (8 rows x 16B) matrices; lane l supplies the row
// address for matrix l>>3, row l&7. Result: reg r = matrix r, lane l holds
// element (row l/4, col l%4) in b32 view — exactly the tf32 A fragment.
__device__ __forceinline__ void ldsm4(uint32_t& r0, uint32_t& r1, uint32_t& r2,
                                      uint32_t& r3, uint32_t addr) {
    asm volatile("ldmatrix.sync.aligned.m8n8.x4.shared.b16 {%0,%1,%2,%3}, [%4];"
                 : "=r"(r0), "=r"(r1), "=r"(r2), "=r"(r3) : "r"(addr));
}

// ---------------- kernel 1: e[b,k] = exp(rowsum(value)/32) ----------------
// warp-per-row: 8 float4 per lane (MLP=8), grid NB*NK/8.
__global__ void k_rowexp(const float* __restrict__ v) {
    int row = blockIdx.x * 8 + (threadIdx.x >> 5);
    int lane = threadIdx.x & 31;
    const float4* p = reinterpret_cast<const float4*>(v + (size_t)row * ND);
    float s = 0.f;
#pragma unroll
    for (int i = 0; i < 8; i++) {
        float4 f = p[lane + i * 32];
        s += (f.x + f.y) + (f.z + f.w);
    }
#pragma unroll
    for (int o = 16; o; o >>= 1) s += __shfl_xor_sync(0xffffffffu, s, o);
    if (lane == 0) g_e[row] = expf(s * 0.03125f);  // / sqrt(1024)
}

// ---------------- kernel 2: weights (softmax closed form) ----------------
// scores = (q_sum[q] + k_sum[k])/32 + mask_bias; q_sum is constant along the
// softmax axis so it cancels: w[b,q,k] = mask * e[b,k] / sum_k(mask * e[b,k]).
// Written tf32-RNA-rounded (w is all-positive: truncation there would bias).
__global__ void k_weights(const int* __restrict__ mask, float* __restrict__ w) {
    int row = blockIdx.x;      // b*NQ + q
    int b = row >> 11;
    const int4* m4 = reinterpret_cast<const int4*>(mask + (size_t)row * NK);
    const float4* e4 = reinterpret_cast<const float4*>(g_e + b * NK);
    float4* w4 = reinterpret_cast<float4*>(w + (size_t)row * NK);
    float s = 0.f;
#pragma unroll
    for (int i = threadIdx.x; i < NK / 4; i += 256) {
        int4 m = m4[i];
        float4 e = e4[i];
        s += (m.x ? e.x : 0.f) + (m.y ? e.y : 0.f) + (m.z ? e.z : 0.f) + (m.w ? e.w : 0.f);
    }
#pragma unroll
    for (int o = 16; o; o >>= 1) s += __shfl_xor_sync(0xffffffffu, s, o);
    __shared__ float sh[8];
    __shared__ float shi;
    if ((threadIdx.x & 31) == 0) sh[threadIdx.x >> 5] = s;
    __syncthreads();
    if (threadIdx.x == 0) {
        float t = 0.f;
#pragma unroll
        for (int i = 0; i < 8; i++) t += sh[i];
        shi = 1.0f / t;
    }
    __syncthreads();
    float inv = shi;
#pragma unroll
    for (int i = threadIdx.x; i < NK / 4; i += 256) {
        int4 m = m4[i];
        float4 e = e4[i];
        float4 o;
        o.x = m.x ? tf32r(e.x * inv) : 0.f;
        o.y = m.y ? tf32r(e.y * inv) : 0.f;
        o.z = m.z ? tf32r(e.z * inv) : 0.f;
        o.w = m.w ? tf32r(e.w * inv) : 0.f;
        w4[i] = o;
    }
}

// ---------------- kernel 3: context = w @ value  (tf32 mma.sync) ----------------
// CTA tile 128x128x32, 8 warps in 2(M) x 4(N), warp tile 64x32, 2 CTAs/SM.
// A fragments via ldmatrix (4 LDSM/chunk); B scalar LDS (8/chunk); B consumed
// raw (HW reads tf32 bits only; value is zero-mean so truncation bias ~6e-5).
#define BM 128
#define BN 128
#define BK 32
#define NT (NK / BK)       // 64
#define ASTRIDE 36         // floats per A smem row (LDSM rows 144B apart: conflict-free)
#define BSTRIDE 136        // floats per B smem row (128 data + 8 pad; frag banks 8t4+g: conflict-free)
#define ABYTES (BM * ASTRIDE * 4)            // 18432
#define BBYTES (BK * BSTRIDE * 4)            // 17408
#define STAGE_BYTES (ABYTES + BBYTES)        // 35840
#define STAGES 3
#define SMEM_GEMM (STAGES * STAGE_BYTES)     // 107520  (x2 CTAs = 210KB <= 228KB/SM)

__global__ void __launch_bounds__(256, 2)
k_gemm(const float* __restrict__ w, const float* __restrict__ value,
       float* __restrict__ ctx) {
    extern __shared__ char smem[];
    uint32_t sb = smem_u32(smem);
    int tid = threadIdx.x, wid = tid >> 5, lane = tid & 31;
    int g = lane >> 2, t4 = lane & 3;
    int d0 = blockIdx.x * BN;
    int q0 = blockIdx.y * BM;
    int b = blockIdx.z;
    int wm = (wid >> 2) * 64;   // warp M offset in CTA tile
    int wn = (wid & 3) * 32;    // warp N offset in CTA tile

    const float* Ag = w + (size_t)(b * NQ + q0) * NK;        // [128 rows q][k]
    const float* Bg = value + (size_t)b * NK * ND + d0;      // [k][128 cols d]

    // per-thread invariant offsets
    const uint32_t a_goff = (uint32_t)((tid >> 3) * NK + (tid & 7) * 4);
    const uint32_t b_goff = (uint32_t)((tid >> 5) * ND + (tid & 31) * 4);
    const uint32_t a_soff = (uint32_t)((tid >> 3) * (ASTRIDE * 4) + (tid & 7) * 16);
    const uint32_t b_soff = (uint32_t)((tid >> 5) * (BSTRIDE * 4) + (tid & 31) * 16);

    auto load_tile = [&](int t, int s) {
        uint32_t k0 = (uint32_t)t * BK;
        uint32_t As = sb + s * STAGE_BYTES;
        uint32_t Bs = As + ABYTES;
        const float* ap = Ag + a_goff + k0;
        const float* bp = Bg + (size_t)(k0) * ND + b_goff;
#pragma unroll
        for (int j = 0; j < 4; j++)   // A: 128 rows x 32 floats, +32 rows per j
            cp16(As + a_soff + (uint32_t)j * (32 * ASTRIDE * 4), ap + (size_t)j * 32 * NK);
#pragma unroll
        for (int j = 0; j < 4; j++)   // B: 32 rows x 128 floats, +8 rows per j
            cp16(Bs + b_soff + (uint32_t)j * (8 * BSTRIDE * 4), bp + (size_t)j * 8 * ND);
        asm volatile("cp.async.commit_group;\n" ::: "memory");
    };

    float acc[4][4][4];
#pragma unroll
    for (int m = 0; m < 4; m++)
#pragma unroll
        for (int n = 0; n < 4; n++)
#pragma unroll
            for (int i = 0; i < 4; i++) acc[m][n][i] = 0.f;

    load_tile(0, 0);
    load_tile(1, 1);

    // ldmatrix lane address base for A: matrix = lane>>3 selects {row+8}x{col+4}
    // quadrant; row l&7 within it.
    const uint32_t aldm0 = (uint32_t)(
        ((wm + (lane & 7) + ((lane >> 3) & 1) * 8) * ASTRIDE) * 4 + (lane >> 4) * 16);
    // B fragment base: (k=t4, n=wn+g)
    const uint32_t bfrag0 = (uint32_t)((t4 * BSTRIDE + wn + g) * 4);

#pragma unroll 1
    for (int t = 0; t < NT; t++) {
        if (t + 2 < NT) asm volatile("cp.async.wait_group 1;\n" ::: "memory");
        else            asm volatile("cp.async.wait_group 0;\n" ::: "memory");
        __syncthreads();
        if (t + 2 < NT) load_tile(t + 2, (t + 2) % 3);

        uint32_t As = sb + (t % 3) * STAGE_BYTES;
        uint32_t Bs = As + ABYTES;
#pragma unroll
        for (int c = 0; c < 4; c++) {
            uint32_t a[4][4];
            float bf[4][2];
#pragma unroll
            for (int m = 0; m < 4; m++)
                ldsm4(a[m][0], a[m][1], a[m][2], a[m][3],
                      As + aldm0 + (uint32_t)(m * 16 * ASTRIDE * 4 + c * 32));
#pragma unroll
            for (int n = 0; n < 4; n++) {
                uint32_t base = Bs + bfrag0 + (uint32_t)(c * 8 * BSTRIDE * 4 + n * 32);
                bf[n][0] = lds32(base);
                bf[n][1] = lds32(base + 4 * BSTRIDE * 4);
            }
#pragma unroll
            for (int m = 0; m < 4; m++)
#pragma unroll
                for (int n = 0; n < 4; n++) {
                    asm volatile(
                        "mma.sync.aligned.m16n8k8.row.col.f32.tf32.tf32.f32 "
                        "{%0,%1,%2,%3}, {%4,%5,%6,%7}, {%8,%9}, {%0,%1,%2,%3};"
                        : "+f"(acc[m][n][0]), "+f"(acc[m][n][1]),
                          "+f"(acc[m][n][2]), "+f"(acc[m][n][3])
                        : "r"(a[m][0]), "r"(a[m][1]), "r"(a[m][2]), "r"(a[m][3]),
                          "r"(__float_as_uint(bf[n][0])), "r"(__float_as_uint(bf[n][1])));
                }
        }
    }

    // epilogue: c0=(g,2t), c1=(g,2t+1), c2=(g+8,2t), c3=(g+8,2t+1)
#pragma unroll
    for (int m = 0; m < 4; m++) {
        int row = q0 + wm + m * 16 + g;
#pragma unroll
        for (int n = 0; n < 4; n++) {
            int col = d0 + wn + n * 8 + 2 * t4;
            float* p0 = ctx + (size_t)(b * NQ + row) * ND + col;
            float* p1 = ctx + (size_t)(b * NQ + row + 8) * ND + col;
            *reinterpret_cast<float2*>(p0) = make_float2(acc[m][n][0], acc[m][n][1]);
            *reinterpret_cast<float2*>(p1) = make_float2(acc[m][n][2], acc[m][n][3]);
        }
    }
}

// ---------------- launcher ----------------
extern "C" void kernel_launch(void* const* d_in, const int* in_sizes, int n_in,
                              void* d_out, int out_size) {
    // inputs: [0]=query (UNUSED: q_sum cancels in softmax), [1]=value, [2]=attention_mask
    const float* value = (const float*)d_in[1];
    const int* mask = (const int*)d_in[2];

    const size_t CTXN = (size_t)NB * NQ * ND;   // 8,388,608
    const size_t WN   = (size_t)NB * NQ * NK;   // 16,777,216

    // Resolve output layout from out_size (defensive: never write past d_out).
    float* ctx;
    float* w;
    void* scr_w = nullptr;
    void* scr_ctx = nullptr;
    cudaGetSymbolAddress(&scr_w, g_w);
    cudaGetSymbolAddress(&scr_ctx, g_ctx);

    if ((size_t)out_size >= CTXN + WN) {
        // [context | attention_weights] concatenated (tuple order)
        ctx = (float*)d_out;
        w = (float*)d_out + CTXN;
    } else if ((size_t)out_size == WN) {
        // weights-only output
        w = (float*)d_out;
        ctx = (float*)scr_ctx;
    } else {
        // context-only output; weights live in scratch (still needed as GEMM A)
        ctx = (float*)d_out;
        w = (float*)scr_w;
    }

    cudaFuncSetAttribute(k_gemm, cudaFuncAttributeMaxDynamicSharedMemorySize, SMEM_GEMM);

    k_rowexp<<<NB * NK / 8, 256>>>(value);
    k_weights<<<NB * NQ, 256>>>(mask, w);
    k_gemm<<<dim3(ND / BN, NQ / BM, NB), 256, SMEM_GEMM>>>(w, value, ctx);
}

// round 13
// speedup vs baseline: 1.2372x; 1.0064x over previous
#include <cuda_runtime.h>
#include <cstdint>

#define NB 4
#define NQ 2048
#define NK 2048
#define ND 1024

// ---------------- device scratch (no runtime allocation allowed) ----------------
__device__ float g_e[NB * NK];                         // exp(rowsum(value)/32)
__device__ float g_w[(size_t)NB * NQ * NK];            // weights scratch (if not in d_out)
__device__ float g_ctx[(size_t)NB * NQ * ND];          // context scratch (if not in d_out)

// ---------------- helpers ----------------
__device__ __forceinline__ uint32_t smem_u32(const void* p) {
    uint32_t a;
    asm("{ .reg .u64 t; cvta.to.shared.u64 t, %1; cvt.u32.u64 %0, t; }" : "=r"(a) : "l"(p));
    return a;
}

__device__ __forceinline__ void cp16(uint32_t s, const void* g) {
    asm volatile("cp.async.cg.shared.global [%0], [%1], 16;\n" :: "r"(s), "l"(g));
}

__device__ __forceinline__ float tf32r(float x) {
    float r;
    asm("cvt.rna.tf32.f32 %0, %1;" : "=f"(r) : "f"(x));
    return r;
}

__device__ __forceinline__ float lds32(uint32_t a) {
    float v;
    asm volatile("ld.shared.b32 %0, [%1];" : "=f"(v) : "r"(a));
    return v;
}

// ldmatrix x4: four 8x4-float (8 rows x 16B) matrices; lane l supplies the row
// address for matrix l>>3, row l&7. Result: reg r = matrix r, lane l holds
// element (row l/4, col l%4) in b32 view — exactly the tf32 A fragment.
__device__ __forceinline__ void ldsm4(uint32_t& r0, uint32_t& r1, uint32_t& r2,
                                      uint32_t& r3, uint32_t addr) {
    asm volatile("ldmatrix.sync.aligned.m8n8.x4.shared.b16 {%0,%1,%2,%3}, [%4];"
                 : "=r"(r0), "=r"(r1), "=r"(r2), "=r"(r3) : "r"(addr));
}

// ---------------- kernel 1: e[b,k] = exp(rowsum(value)/32) ----------------
// warp-per-row: 8 float4 per lane (MLP=8), grid NB*NK/8.
__global__ void k_rowexp(const float* __restrict__ v) {
    int row = blockIdx.x * 8 + (threadIdx.x >> 5);
    int lane = threadIdx.x & 31;
    const float4* p = reinterpret_cast<const float4*>(v + (size_t)row * ND);
    float s = 0.f;
#pragma unroll
    for (int i = 0; i < 8; i++) {
        float4 f = p[lane + i * 32];
        s += (f.x + f.y) + (f.z + f.w);
    }
#pragma unroll
    for (int o = 16; o; o >>= 1) s += __shfl_xor_sync(0xffffffffu, s, o);
    if (lane == 0) g_e[row] = expf(s * 0.03125f);  // / sqrt(1024)
}

// ---------------- kernel 2: weights (softmax closed form) ----------------
// scores = (q_sum[q] + k_sum[k])/32 + mask_bias; q_sum is constant along the
// softmax axis so it cancels: w[b,q,k] = mask * e[b,k] / sum_k(mask * e[b,k]).
// Single pass: each thread keeps its 2 int4 + 2 float4 in registers across the
// block reduction (mask read ONCE: 67MB reads + 64MB writes, was 134+64).
// Written tf32-RNA-rounded (w is all-positive: truncation there would bias).
__global__ void k_weights(const int* __restrict__ mask, float* __restrict__ w) {
    int row = blockIdx.x;      // b*NQ + q
    int b = row >> 11;
    const int4* m4 = reinterpret_cast<const int4*>(mask + (size_t)row * NK);
    const float4* e4 = reinterpret_cast<const float4*>(g_e + b * NK);
    float4* w4 = reinterpret_cast<float4*>(w + (size_t)row * NK);

    int i0 = threadIdx.x, i1 = threadIdx.x + 256;   // NK/4 = 512 = 2*256
    int4 m0 = m4[i0], m1 = m4[i1];
    float4 e0 = e4[i0], e1 = e4[i1];

    float s = (m0.x ? e0.x : 0.f) + (m0.y ? e0.y : 0.f) +
              (m0.z ? e0.z : 0.f) + (m0.w ? e0.w : 0.f) +
              (m1.x ? e1.x : 0.f) + (m1.y ? e1.y : 0.f) +
              (m1.z ? e1.z : 0.f) + (m1.w ? e1.w : 0.f);
#pragma unroll
    for (int o = 16; o; o >>= 1) s += __shfl_xor_sync(0xffffffffu, s, o);
    __shared__ float sh[8];
    __shared__ float shi;
    if ((threadIdx.x & 31) == 0) sh[threadIdx.x >> 5] = s;
    __syncthreads();
    if (threadIdx.x == 0) {
        float t = 0.f;
#pragma unroll
        for (int i = 0; i < 8; i++) t += sh[i];
        shi = 1.0f / t;
    }
    __syncthreads();
    float inv = shi;

    float4 o0, o1;
    o0.x = m0.x ? tf32r(e0.x * inv) : 0.f;
    o0.y = m0.y ? tf32r(e0.y * inv) : 0.f;
    o0.z = m0.z ? tf32r(e0.z * inv) : 0.f;
    o0.w = m0.w ? tf32r(e0.w * inv) : 0.f;
    o1.x = m1.x ? tf32r(e1.x * inv) : 0.f;
    o1.y = m1.y ? tf32r(e1.y * inv) : 0.f;
    o1.z = m1.z ? tf32r(e1.z * inv) : 0.f;
    o1.w = m1.w ? tf32r(e1.w * inv) : 0.f;
    w4[i0] = o0;
    w4[i1] = o1;
}

// ---------------- kernel 3: context = w @ value  (tf32 mma.sync) ----------------
// CTA tile 128x128x32, 8 warps in 2(M) x 4(N), warp tile 64x32, 2 CTAs/SM.
// A fragments via ldmatrix (4 LDSM/chunk); B scalar LDS (8/chunk); B consumed
// raw (HW reads tf32 bits only; value is zero-mean so truncation bias ~6e-5).
#define BM 128
#define BN 128
#define BK 32
#define NT (NK / BK)       // 64
#define ASTRIDE 36         // floats per A smem row (LDSM rows 144B apart: conflict-free)
#define BSTRIDE 136        // floats per B smem row (128 data + 8 pad; frag banks 8t4+g: conflict-free)
#define ABYTES (BM * ASTRIDE * 4)            // 18432
#define BBYTES (BK * BSTRIDE * 4)            // 17408
#define STAGE_BYTES (ABYTES + BBYTES)        // 35840
#define STAGES 3
#define SMEM_GEMM (STAGES * STAGE_BYTES)     // 107520  (x2 CTAs = 210KB <= 228KB/SM)

__global__ void __launch_bounds__(256, 2)
k_gemm(const float* __restrict__ w, const float* __restrict__ value,
       float* __restrict__ ctx) {
    extern __shared__ char smem[];
    uint32_t sb = smem_u32(smem);
    int tid = threadIdx.x, wid = tid >> 5, lane = tid & 31;
    int g = lane >> 2, t4 = lane & 3;
    int d0 = blockIdx.x * BN;
    int q0 = blockIdx.y * BM;
    int b = blockIdx.z;
    int wm = (wid >> 2) * 64;   // warp M offset in CTA tile
    int wn = (wid & 3) * 32;    // warp N offset in CTA tile

    const float* Ag = w + (size_t)(b * NQ + q0) * NK;        // [128 rows q][k]
    const float* Bg = value + (size_t)b * NK * ND + d0;      // [k][128 cols d]

    // per-thread invariant offsets
    const uint32_t a_goff = (uint32_t)((tid >> 3) * NK + (tid & 7) * 4);
    const uint32_t b_goff = (uint32_t)((tid >> 5) * ND + (tid & 31) * 4);
    const uint32_t a_soff = (uint32_t)((tid >> 3) * (ASTRIDE * 4) + (tid & 7) * 16);
    const uint32_t b_soff = (uint32_t)((tid >> 5) * (BSTRIDE * 4) + (tid & 31) * 16);

    auto load_tile = [&](int t, int s) {
        uint32_t k0 = (uint32_t)t * BK;
        uint32_t As = sb + s * STAGE_BYTES;
        uint32_t Bs = As + ABYTES;
        const float* ap = Ag + a_goff + k0;
        const float* bp = Bg + (size_t)(k0) * ND + b_goff;
#pragma unroll
        for (int j = 0; j < 4; j++)   // A: 128 rows x 32 floats, +32 rows per j
            cp16(As + a_soff + (uint32_t)j * (32 * ASTRIDE * 4), ap + (size_t)j * 32 * NK);
#pragma unroll
        for (int j = 0; j < 4; j++)   // B: 32 rows x 128 floats, +8 rows per j
            cp16(Bs + b_soff + (uint32_t)j * (8 * BSTRIDE * 4), bp + (size_t)j * 8 * ND);
        asm volatile("cp.async.commit_group;\n" ::: "memory");
    };

    float acc[4][4][4];
#pragma unroll
    for (int m = 0; m < 4; m++)
#pragma unroll
        for (int n = 0; n < 4; n++)
#pragma unroll
            for (int i = 0; i < 4; i++) acc[m][n][i] = 0.f;

    load_tile(0, 0);
    load_tile(1, 1);

    // ldmatrix lane address base for A: matrix = lane>>3 selects {row+8}x{col+4}
    // quadrant; row l&7 within it.
    const uint32_t aldm0 = (uint32_t)(
        ((wm + (lane & 7) + ((lane >> 3) & 1) * 8) * ASTRIDE) * 4 + (lane >> 4) * 16);
    // B fragment base: (k=t4, n=wn+g)
    const uint32_t bfrag0 = (uint32_t)((t4 * BSTRIDE + wn + g) * 4);

#pragma unroll 1
    for (int t = 0; t < NT; t++) {
        if (t + 2 < NT) asm volatile("cp.async.wait_group 1;\n" ::: "memory");
        else            asm volatile("cp.async.wait_group 0;\n" ::: "memory");
        __syncthreads();
        if (t + 2 < NT) load_tile(t + 2, (t + 2) % 3);

        uint32_t As = sb + (t % 3) * STAGE_BYTES;
        uint32_t Bs = As + ABYTES;
#pragma unroll
        for (int c = 0; c < 4; c++) {
            uint32_t a[4][4];
            float bf[4][2];
#pragma unroll
            for (int m = 0; m < 4; m++)
                ldsm4(a[m][0], a[m][1], a[m][2], a[m][3],
                      As + aldm0 + (uint32_t)(m * 16 * ASTRIDE * 4 + c * 32));
#pragma unroll
            for (int n = 0; n < 4; n++) {
                uint32_t base = Bs + bfrag0 + (uint32_t)(c * 8 * BSTRIDE * 4 + n * 32);
                bf[n][0] = lds32(base);
                bf[n][1] = lds32(base + 4 * BSTRIDE * 4);
            }
#pragma unroll
            for (int m = 0; m < 4; m++)
#pragma unroll
                for (int n = 0; n < 4; n++) {
                    asm volatile(
                        "mma.sync.aligned.m16n8k8.row.col.f32.tf32.tf32.f32 "
                        "{%0,%1,%2,%3}, {%4,%5,%6,%7}, {%8,%9}, {%0,%1,%2,%3};"
                        : "+f"(acc[m][n][0]), "+f"(acc[m][n][1]),
                          "+f"(acc[m][n][2]), "+f"(acc[m][n][3])
                        : "r"(a[m][0]), "r"(a[m][1]), "r"(a[m][2]), "r"(a[m][3]),
                          "r"(__float_as_uint(bf[n][0])), "r"(__float_as_uint(bf[n][1])));
                }
        }
    }

    // epilogue: c0=(g,2t), c1=(g,2t+1), c2=(g+8,2t), c3=(g+8,2t+1)
#pragma unroll
    for (int m = 0; m < 4; m++) {
        int row = q0 + wm + m * 16 + g;
#pragma unroll
        for (int n = 0; n < 4; n++) {
            int col = d0 + wn + n * 8 + 2 * t4;
            float* p0 = ctx + (size_t)(b * NQ + row) * ND + col;
            float* p1 = ctx + (size_t)(b * NQ + row + 8) * ND + col;
            *reinterpret_cast<float2*>(p0) = make_float2(acc[m][n][0], acc[m][n][1]);
            *reinterpret_cast<float2*>(p1) = make_float2(acc[m][n][2], acc[m][n][3]);
        }
    }
}

// ---------------- launcher ----------------
extern "C" void kernel_launch(void* const* d_in, const int* in_sizes, int n_in,
                              void* d_out, int out_size) {
    // inputs: [0]=query (UNUSED: q_sum cancels in softmax), [1]=value, [2]=attention_mask
    const float* value = (const float*)d_in[1];
    const int* mask = (const int*)d_in[2];

    const size_t CTXN = (size_t)NB * NQ * ND;   // 8,388,608
    const size_t WN   = (size_t)NB * NQ * NK;   // 16,777,216

    // Resolve output layout from out_size (defensive: never write past d_out).
    float* ctx;
    float* w;
    void* scr_w = nullptr;
    void* scr_ctx = nullptr;
    cudaGetSymbolAddress(&scr_w, g_w);
    cudaGetSymbolAddress(&scr_ctx, g_ctx);

    if ((size_t)out_size >= CTXN + WN) {
        // [context | attention_weights] concatenated (tuple order)
        ctx = (float*)d_out;
        w = (float*)d_out + CTXN;
    } else if ((size_t)out_size == WN) {
        // weights-only output
        w = (float*)d_out;
        ctx = (float*)scr_ctx;
    } else {
        // context-only output; weights live in scratch (still needed as GEMM A)
        ctx = (float*)d_out;
        w = (float*)scr_w;
    }

    cudaFuncSetAttribute(k_gemm, cudaFuncAttributeMaxDynamicSharedMemorySize, SMEM_GEMM);

    k_rowexp<<<NB * NK / 8, 256>>>(value);
    k_weights<<<NB * NQ, 256>>>(mask, w);
    k_gemm<<<dim3(ND / BN, NQ / BM, NB), 256, SMEM_GEMM>>>(w, value, ctx);
}

// round 14
// speedup vs baseline: 2.0280x; 1.6392x over previous
#include <cuda_runtime.h>
#include <cuda_fp16.h>
#include <cstdint>

#define NB 4
#define NQ 2048
#define NK 2048
#define ND 1024

// ---------------- device scratch (no runtime allocation allowed) ----------------
__device__ float g_e[NB * NK];                          // exp(rowsum(value)/32)
__device__ float g_w[(size_t)NB * NQ * NK];             // weights scratch (if not in d_out)
__device__ float g_ctx[(size_t)NB * NQ * ND];           // context scratch (if not in d_out)
__device__ __half g_wh[(size_t)NB * NQ * NK];           // fp16(1024*w) GEMM A operand
__device__ __half g_vh[(size_t)NB * NK * ND];           // fp16(value)  GEMM B operand

// ---------------- helpers ----------------
__device__ __forceinline__ uint32_t smem_u32(const void* p) {
    uint32_t a;
    asm("{ .reg .u64 t; cvta.to.shared.u64 t, %1; cvt.u32.u64 %0, t; }" : "=r"(a) : "l"(p));
    return a;
}

__device__ __forceinline__ void cp16(uint32_t s, const void* g) {
    asm volatile("cp.async.cg.shared.global [%0], [%1], 16;\n" :: "r"(s), "l"(g));
}

// ldmatrix x4 (non-trans): 4 8-row x 16B matrices; lane l addresses matrix l>>3's
// row l&7. For f16 A m16n8k16: mat0=rows0-7/k0-7, mat1=rows8-15/k0-7,
// mat2=rows0-7/k8-15, mat3=rows8-15/k8-15 -> regs a0..a3 exactly.
__device__ __forceinline__ void ldsm4(uint32_t& r0, uint32_t& r1, uint32_t& r2,
                                      uint32_t& r3, uint32_t addr) {
    asm volatile("ldmatrix.sync.aligned.m8n8.x4.shared.b16 {%0,%1,%2,%3}, [%4];"
                 : "=r"(r0), "=r"(r1), "=r"(r2), "=r"(r3) : "r"(addr));
}

// ldmatrix x4 trans: B (k-major) -> b fragments. Lanes 0-15: k-row lane&15 of the
// n-lo 16B half; lanes 16-31: same k-rows of n-hi half. Result: reg0/1 = b0/b1 of
// n-block j, reg2/3 = b0/b1 of n-block j+1.
__device__ __forceinline__ void ldsm4t(uint32_t& r0, uint32_t& r1, uint32_t& r2,
                                       uint32_t& r3, uint32_t addr) {
    asm volatile("ldmatrix.sync.aligned.m8n8.x4.trans.shared.b16 {%0,%1,%2,%3}, [%4];"
                 : "=r"(r0), "=r"(r1), "=r"(r2), "=r"(r3) : "r"(addr));
}

// ---------------- kernel 1: e + fp16 copy of value ----------------
// warp-per-row: 8 float4 per lane (MLP=8). Also emits g_vh = fp16(value).
__global__ void k_rowexp(const float* __restrict__ v) {
    int row = blockIdx.x * 8 + (threadIdx.x >> 5);
    int lane = threadIdx.x & 31;
    const float4* p = reinterpret_cast<const float4*>(v + (size_t)row * ND);
    uint2* vh = reinterpret_cast<uint2*>(g_vh + (size_t)row * ND);
    float s = 0.f;
#pragma unroll
    for (int i = 0; i < 8; i++) {
        float4 f = p[lane + i * 32];
        s += (f.x + f.y) + (f.z + f.w);
        __half2 lo = __floats2half2_rn(f.x, f.y);
        __half2 hi = __floats2half2_rn(f.z, f.w);
        uint2 u;
        u.x = *reinterpret_cast<uint32_t*>(&lo);
        u.y = *reinterpret_cast<uint32_t*>(&hi);
        vh[lane + i * 32] = u;
    }
#pragma unroll
    for (int o = 16; o; o >>= 1) s += __shfl_xor_sync(0xffffffffu, s, o);
    if (lane == 0) g_e[row] = expf(s * 0.03125f);  // / sqrt(1024)
}

// ---------------- kernel 2: weights (softmax closed form) ----------------
// w[b,q,k] = mask * e[b,k] / sum_k(mask * e[b,k])  (q_sum cancels in softmax).
// Writes exact fp32 w to the output AND wh = fp16(1024*w) for the GEMM
// (scaling keeps all wh normal; epilogue multiplies by 2^-10 exactly).
__global__ void k_weights(const int* __restrict__ mask, float* __restrict__ w) {
    int row = blockIdx.x;      // b*NQ + q
    int b = row >> 11;
    const int4* m4 = reinterpret_cast<const int4*>(mask + (size_t)row * NK);
    const float4* e4 = reinterpret_cast<const float4*>(g_e + b * NK);
    float4* w4 = reinterpret_cast<float4*>(w + (size_t)row * NK);
    uint2* wh = reinterpret_cast<uint2*>(g_wh + (size_t)row * NK);

    int i0 = threadIdx.x, i1 = threadIdx.x + 256;   // NK/4 = 512 = 2*256
    int4 m0 = m4[i0], m1 = m4[i1];
    float4 e0 = e4[i0], e1 = e4[i1];

    float s = (m0.x ? e0.x : 0.f) + (m0.y ? e0.y : 0.f) +
              (m0.z ? e0.z : 0.f) + (m0.w ? e0.w : 0.f) +
              (m1.x ? e1.x : 0.f) + (m1.y ? e1.y : 0.f) +
              (m1.z ? e1.z : 0.f) + (m1.w ? e1.w : 0.f);
#pragma unroll
    for (int o = 16; o; o >>= 1) s += __shfl_xor_sync(0xffffffffu, s, o);
    __shared__ float sh[8];
    __shared__ float shi;
    if ((threadIdx.x & 31) == 0) sh[threadIdx.x >> 5] = s;
    __syncthreads();
    if (threadIdx.x == 0) {
        float t = 0.f;
#pragma unroll
        for (int i = 0; i < 8; i++) t += sh[i];
        shi = 1.0f / t;
    }
    __syncthreads();
    float inv = shi;
    float inv1024 = inv * 1024.0f;

    float4 o0, o1;
    o0.x = m0.x ? e0.x * inv : 0.f;
    o0.y = m0.y ? e0.y * inv : 0.f;
    o0.z = m0.z ? e0.z * inv : 0.f;
    o0.w = m0.w ? e0.w * inv : 0.f;
    o1.x = m1.x ? e1.x * inv : 0.f;
    o1.y = m1.y ? e1.y * inv : 0.f;
    o1.z = m1.z ? e1.z * inv : 0.f;
    o1.w = m1.w ? e1.w * inv : 0.f;
    w4[i0] = o0;
    w4[i1] = o1;

    float4 h0, h1;
    h0.x = m0.x ? e0.x * inv1024 : 0.f;
    h0.y = m0.y ? e0.y * inv1024 : 0.f;
    h0.z = m0.z ? e0.z * inv1024 : 0.f;
    h0.w = m0.w ? e0.w * inv1024 : 0.f;
    h1.x = m1.x ? e1.x * inv1024 : 0.f;
    h1.y = m1.y ? e1.y * inv1024 : 0.f;
    h1.z = m1.z ? e1.z * inv1024 : 0.f;
    h1.w = m1.w ? e1.w * inv1024 : 0.f;
    {
        __half2 lo = __floats2half2_rn(h0.x, h0.y), hi = __floats2half2_rn(h0.z, h0.w);
        uint2 u;
        u.x = *reinterpret_cast<uint32_t*>(&lo);
        u.y = *reinterpret_cast<uint32_t*>(&hi);
        wh[i0] = u;
        lo = __floats2half2_rn(h1.x, h1.y); hi = __floats2half2_rn(h1.z, h1.w);
        u.x = *reinterpret_cast<uint32_t*>(&lo);
        u.y = *reinterpret_cast<uint32_t*>(&hi);
        wh[i1] = u;
    }
}

// ---------------- kernel 3: context = (wh @ vh) * 2^-10  (fp16 mma.sync) -----
// CTA tile 128x128x64, 8 warps in 2(M) x 4(N), warp tile 64x32, 2 CTAs/SM.
// fp16 has the SAME 11-bit significand as tf32; fp32 accumulation.
#define BM 128
#define BN 128
#define BK 64
#define NT (NK / BK)       // 32
#define ASTB 144           // bytes per A smem row (128 data + 16 pad; ldsm rows distinct groups)
#define BSTB 272           // bytes per B smem row (256 data + 16 pad; ldsm.trans rows distinct)
#define ABYTES (BM * ASTB)                   // 18432
#define BBYTES (BK * BSTB)                   // 17408
#define STAGE_BYTES (ABYTES + BBYTES)        // 35840
#define STAGES 3
#define SMEM_GEMM (STAGES * STAGE_BYTES)     // 107520  (x2 CTAs = 210KB <= 228KB/SM)

__global__ void __launch_bounds__(256, 2)
k_gemm(float* __restrict__ ctx) {
    extern __shared__ char smem[];
    uint32_t sb = smem_u32(smem);
    int tid = threadIdx.x, wid = tid >> 5, lane = tid & 31;
    int g = lane >> 2, t4 = lane & 3;
    int d0 = blockIdx.x * BN;
    int q0 = blockIdx.y * BM;
    int b = blockIdx.z;
    int wm = (wid >> 2) * 64;   // warp M offset in CTA tile
    int wn = (wid & 3) * 32;    // warp N offset in CTA tile

    const __half* Ag = g_wh + (size_t)(b * NQ + q0) * NK;     // [128 rows q][k] f16
    const __half* Bg = g_vh + (size_t)b * NK * ND + d0;       // [k][128 cols d] f16

    // cp.async thread-invariant offsets
    // A: 128 rows x 8 chunks(16B); task = tid + j*256, r=task>>3, c=task&7
    const uint32_t a_goff = (uint32_t)((tid >> 3) * NK + (tid & 7) * 8);
    const uint32_t a_soff = (uint32_t)((tid >> 3) * ASTB + (tid & 7) * 16);
    // B: 64 rows x 16 chunks(16B); r=task>>4, c=task&15
    const uint32_t b_goff = (uint32_t)((tid >> 4) * ND + (tid & 15) * 8);
    const uint32_t b_soff = (uint32_t)((tid >> 4) * BSTB + (tid & 15) * 16);

    auto load_tile = [&](int t, int s) {
        uint32_t k0 = (uint32_t)t * BK;
        uint32_t As = sb + s * STAGE_BYTES;
        uint32_t Bs = As + ABYTES;
        const __half* ap = Ag + a_goff + k0;
        const __half* bp = Bg + (size_t)k0 * ND + b_goff;
#pragma unroll
        for (int j = 0; j < 4; j++)   // A: +32 rows per j
            cp16(As + a_soff + (uint32_t)j * (32 * ASTB), ap + (size_t)j * 32 * NK);
#pragma unroll
        for (int j = 0; j < 4; j++)   // B: +16 rows per j
            cp16(Bs + b_soff + (uint32_t)j * (16 * BSTB), bp + (size_t)j * 16 * ND);
        asm volatile("cp.async.commit_group;\n" ::: "memory");
    };

    float acc[4][4][4];
#pragma unroll
    for (int m = 0; m < 4; m++)
#pragma unroll
        for (int n = 0; n < 4; n++)
#pragma unroll
            for (int i = 0; i < 4; i++) acc[m][n][i] = 0.f;

    load_tile(0, 0);
    load_tile(1, 1);

    // A ldmatrix lane base: row = wm + (l&7) + ((l>>3)&1)*8 ; k-16B-half = l>>4
    const uint32_t aldm0 = (uint32_t)(
        (wm + (lane & 7) + ((lane >> 3) & 1) * 8) * ASTB + (lane >> 4) * 16);
    // B ldmatrix.trans lane base: k-row = l&15 ; n-16B-half = l>>4 ; n base = wn
    const uint32_t bldm0 = (uint32_t)((lane & 15) * BSTB + (lane >> 4) * 16 + wn * 2);

#pragma unroll 1
    for (int t = 0; t < NT; t++) {
        if (t + 2 < NT) asm volatile("cp.async.wait_group 1;\n" ::: "memory");
        else            asm volatile("cp.async.wait_group 0;\n" ::: "memory");
        __syncthreads();
        if (t + 2 < NT) load_tile(t + 2, (t + 2) % 3);

        uint32_t As = sb + (t % 3) * STAGE_BYTES;
        uint32_t Bs = As + ABYTES;
#pragma unroll
        for (int c = 0; c < 4; c++) {    // 4 chunks of K=16
            uint32_t a[4][4], bb[4][2];
#pragma unroll
            for (int m = 0; m < 4; m++)
                ldsm4(a[m][0], a[m][1], a[m][2], a[m][3],
                      As + aldm0 + (uint32_t)(m * 16 * ASTB + c * 32));
            // two trans loads: n-blocks {0,1} and {2,3} of the warp's 32-wide n
            ldsm4t(bb[0][0], bb[0][1], bb[1][0], bb[1][1],
                   Bs + bldm0 + (uint32_t)(c * 16 * BSTB));
            ldsm4t(bb[2][0], bb[2][1], bb[3][0], bb[3][1],
                   Bs + bldm0 + (uint32_t)(c * 16 * BSTB + 32));
#pragma unroll
            for (int m = 0; m < 4; m++)
#pragma unroll
                for (int n = 0; n < 4; n++) {
                    asm volatile(
                        "mma.sync.aligned.m16n8k16.row.col.f32.f16.f16.f32 "
                        "{%0,%1,%2,%3}, {%4,%5,%6,%7}, {%8,%9}, {%0,%1,%2,%3};"
                        : "+f"(acc[m][n][0]), "+f"(acc[m][n][1]),
                          "+f"(acc[m][n][2]), "+f"(acc[m][n][3])
                        : "r"(a[m][0]), "r"(a[m][1]), "r"(a[m][2]), "r"(a[m][3]),
                          "r"(bb[n][0]), "r"(bb[n][1]));
                }
        }
    }

    // epilogue: undo the 1024x A scaling (exact power of two).
    const float sc = 1.0f / 1024.0f;
#pragma unroll
    for (int m = 0; m < 4; m++) {
        int row = q0 + wm + m * 16 + g;
#pragma unroll
        for (int n = 0; n < 4; n++) {
            int col = d0 + wn + n * 8 + 2 * t4;
            float* p0 = ctx + (size_t)(b * NQ + row) * ND + col;
            float* p1 = ctx + (size_t)(b * NQ + row + 8) * ND + col;
            *reinterpret_cast<float2*>(p0) = make_float2(acc[m][n][0] * sc, acc[m][n][1] * sc);
            *reinterpret_cast<float2*>(p1) = make_float2(acc[m][n][2] * sc, acc[m][n][3] * sc);
        }
    }
}

// ---------------- launcher ----------------
extern "C" void kernel_launch(void* const* d_in, const int* in_sizes, int n_in,
                              void* d_out, int out_size) {
    // inputs: [0]=query (UNUSED: q_sum cancels in softmax), [1]=value, [2]=attention_mask
    const float* value = (const float*)d_in[1];
    const int* mask = (const int*)d_in[2];

    const size_t CTXN = (size_t)NB * NQ * ND;   // 8,388,608
    const size_t WN   = (size_t)NB * NQ * NK;   // 16,777,216

    // Resolve output layout from out_size (defensive: never write past d_out).
    float* ctx;
    float* w;
    void* scr_w = nullptr;
    void* scr_ctx = nullptr;
    cudaGetSymbolAddress(&scr_w, g_w);
    cudaGetSymbolAddress(&scr_ctx, g_ctx);

    if ((size_t)out_size >= CTXN + WN) {
        // [context | attention_weights] concatenated (tuple order)
        ctx = (float*)d_out;
        w = (float*)d_out + CTXN;
    } else if ((size_t)out_size == WN) {
        // weights-only output
        w = (float*)d_out;
        ctx = (float*)scr_ctx;
    } else {
        // context-only output
        ctx = (float*)d_out;
        w = (float*)scr_w;
    }

    cudaFuncSetAttribute(k_gemm, cudaFuncAttributeMaxDynamicSharedMemorySize, SMEM_GEMM);

    k_rowexp<<<NB * NK / 8, 256>>>(value);
    k_weights<<<NB * NQ, 256>>>(mask, w);
    k_gemm<<<dim3(ND / BN, NQ / BM, NB), 256, SMEM_GEMM>>>(ctx);
}